// round 13
// baseline (speedup 1.0000x reference)
#include <cuda_runtime.h>
#include <cuda_fp16.h>
#include <math.h>
#include <stdint.h>

#define SD 8192
#define HD 1024
#define NCHUNK 32                 // = SD / BM

#define BM 256
#define BN 128
#define BKH 32                    // K halves per chunk
#define TPAD 40                   // smem row stride (halves)
#define A_TILE_BYTES (BM * TPAD * 2)       // 20480
#define B_TILE_BYTES (BN * TPAD * 2)       // 10240
#define STAGE_BYTES (2 * A_TILE_BYTES + 2 * B_TILE_BYTES)  // 61440
#define NSTG 3
#define SMEM_TOTAL (NSTG * STAGE_BYTES)    // 184320
#define NK (HD / BKH)             // 32
#define MSHIFT 100.0f
#define NT 512                    // threads per CTA (16 warps)

// ---------------- device scratch (no allocations) --------------------------
static __device__ __half g_eh[SD * HD], g_el[SD * HD];
static __device__ __half g_w1h[HD * HD], g_w1l[HD * HD];
static __device__ __half g_w2h[HD * HD], g_w2l[HD * HD];
static __device__ __half g_qh[SD * HD], g_ql[SD * HD];
static __device__ __half g_kh[SD * HD], g_kl[SD * HD];
static __device__ float  g_scores[(size_t)SD * SD];
static __device__ float  g_colinv[SD];
static __device__ float  g_colsum_part[NCHUNK][SD];

// ---------------- helpers ---------------------------------------------------
__device__ __forceinline__ void cp16(uint32_t dst, const void* src) {
    asm volatile("cp.async.cg.shared.global [%0], [%1], 16;" :: "r"(dst), "l"(src));
}
#define CP_COMMIT() asm volatile("cp.async.commit_group;" ::: "memory")
#define CP_WAIT(n)  asm volatile("cp.async.wait_group %0;" :: "n"(n) : "memory")

__device__ __forceinline__ uint32_t smem_u32(const void* p) {
    uint32_t a;
    asm("{ .reg .u64 t; cvta.to.shared.u64 t, %1; cvt.u32.u64 %0, t; }"
        : "=r"(a) : "l"(p));
    return a;
}

__device__ __forceinline__ void mma16816(float* c, const uint32_t* a, const uint32_t* b) {
    asm volatile(
        "mma.sync.aligned.m16n8k16.row.col.f32.f16.f16.f32 "
        "{%0,%1,%2,%3}, {%4,%5,%6,%7}, {%8,%9}, {%0,%1,%2,%3};\n"
        : "+f"(c[0]), "+f"(c[1]), "+f"(c[2]), "+f"(c[3])
        : "r"(a[0]), "r"(a[1]), "r"(a[2]), "r"(a[3]), "r"(b[0]), "r"(b[1]));
}

__device__ __forceinline__ void ldm_x4(uint32_t addr, uint32_t* r) {
    asm volatile("ldmatrix.sync.aligned.m8n8.x4.shared.b16 {%0,%1,%2,%3}, [%4];"
        : "=r"(r[0]), "=r"(r[1]), "=r"(r[2]), "=r"(r[3]) : "r"(addr));
}

// ---------------- split fp32 -> fp16 hi/lo planes ---------------------------
__global__ __launch_bounds__(256) void split_half_kernel(
    const float* __restrict__ src, __half* __restrict__ hi,
    __half* __restrict__ lo, int n4) {
    int i = blockIdx.x * 256 + threadIdx.x;
    if (i >= n4) return;
    float4 v = ((const float4*)src)[i];
    __half h0 = __float2half_rn(v.x), h1 = __float2half_rn(v.y);
    __half h2 = __float2half_rn(v.z), h3 = __float2half_rn(v.w);
    __half l0 = __float2half_rn(v.x - __half2float(h0));
    __half l1 = __float2half_rn(v.y - __half2float(h1));
    __half l2 = __float2half_rn(v.z - __half2float(h2));
    __half l3 = __float2half_rn(v.w - __half2float(h3));
    ((__half2*)hi)[i * 2]     = __halves2half2(h0, h1);
    ((__half2*)hi)[i * 2 + 1] = __halves2half2(h2, h3);
    ((__half2*)lo)[i * 2]     = __halves2half2(l0, l1);
    ((__half2*)lo)[i * 2 + 1] = __halves2half2(l2, l3);
}

// ---------------- split-fp16 tensor-core GEMM: C[BM,BN] = A @ B^T -----------
// 512 threads, 16 warps in 4x4 grid, warp tile 64x32.
// EPI 0: scores + fused deterministic column exp-sums (shift M=100)
// EPI 1: merged q/k — blockIdx.z picks weights/outputs; z==0 applies tanh
template <int EPI>
__global__ __launch_bounds__(NT, 1) void gemm_hmma(
    const __half* __restrict__ Ah, const __half* __restrict__ Al,
    const __half* __restrict__ B1h, const __half* __restrict__ B1l,
    const __half* __restrict__ B2h, const __half* __restrict__ B2l,
    float* __restrict__ outS,
    __half* __restrict__ o1H, __half* __restrict__ o1L,
    __half* __restrict__ o2H, __half* __restrict__ o2L) {
    extern __shared__ char smem[];
    const uint32_t su_base = smem_u32(smem);
    const int tid = threadIdx.x;
    const int wid = tid >> 5, lane = tid & 31;
    const int wm = wid >> 2, wn = wid & 3;       // 4x4 warp grid, tile 64x32
    const int lr = lane >> 2, lc2 = (lane & 3) * 2;

    const int z = (EPI == 1) ? blockIdx.z : 0;
    const __half* Bh = (EPI == 1 && z) ? B2h : B1h;
    const __half* Bl = (EPI == 1 && z) ? B2l : B1l;
    __half* outH = (EPI == 1) ? (z ? o2H : o1H) : (__half*)0;
    __half* outL = (EPI == 1) ? (z ? o2L : o1L) : (__half*)0;
    const bool dotanh = (EPI == 1) && (z == 0);

    // supertile remap (8 M-tiles per N panel stay L2-hot)
    int id = blockIdx.y * gridDim.x + blockIdx.x;
    const int G = 8;
    int perG = gridDim.x * G;
    int by = (id / perG) * G + ((id % perG) % G);
    int bx = (id % perG) / G;

    const size_t rowA0 = (size_t)by * BM;
    const size_t rowB0 = (size_t)bx * BN;

    // ldmatrix per-lane byte offsets within a tile
    const uint32_t aoff =
        ((uint32_t)((wm * 64 + (lane & 7) + ((lane >> 3) & 1) * 8) * TPAD +
                    ((lane >> 4) & 1) * 8)) * 2;
    const uint32_t boff =
        ((uint32_t)((wn * 32 + ((lane >> 4) & 1) * 8 + (lane & 7)) * TPAD +
                    ((lane >> 3) & 1) * 8)) * 2;

    float acc[4][4][4];
#pragma unroll
    for (int a = 0; a < 4; a++)
#pragma unroll
        for (int b = 0; b < 4; b++)
#pragma unroll
            for (int c = 0; c < 4; c++) acc[a][b][c] = 0.0f;

    // ---- async load one k-chunk into stage s (6 cp16 per thread) ----
    auto load_stage = [&](int s, int kc) {
        const int k0 = kc * BKH;
        uint32_t sb = su_base + s * STAGE_BYTES;
#pragma unroll
        for (int t = 0; t < 4; t++) {          // A planes: idx 0..2047
            int idx = tid + t * NT;
            int plane = idx >> 10;
            int r = (idx >> 2) & 255;
            int c = idx & 3;
            const __half* src = (plane ? Al : Ah) + (rowA0 + r) * HD + k0 + c * 8;
            cp16(sb + plane * A_TILE_BYTES + (r * TPAD + c * 8) * 2, src);
        }
#pragma unroll
        for (int t = 0; t < 2; t++) {          // B planes: idx 0..1023
            int idx = tid + t * NT;
            int plane = idx >> 9;
            int r = (idx >> 2) & 127;
            int c = idx & 3;
            const __half* src = (plane ? Bl : Bh) + (rowB0 + r) * HD + k0 + c * 8;
            cp16(sb + 2 * A_TILE_BYTES + plane * B_TILE_BYTES + (r * TPAD + c * 8) * 2, src);
        }
    };

    load_stage(0, 0); CP_COMMIT();
    load_stage(1, 1); CP_COMMIT();

    for (int it = 0; it < NK; it++) {
        CP_WAIT(1);
        __syncthreads();
        const uint32_t sbase = su_base + (it % NSTG) * STAGE_BYTES;
        const uint32_t aAh = sbase + aoff;
        const uint32_t aAl = sbase + A_TILE_BYTES + aoff;
        const uint32_t aBh = sbase + 2 * A_TILE_BYTES + boff;
        const uint32_t aBl = sbase + 2 * A_TILE_BYTES + B_TILE_BYTES + boff;

        uint32_t bh[4][2], bl[4][2], af[4][4];
        // ---- ks = 0: latency-critical fragment loads FIRST
        {
            uint32_t t[4];
            ldm_x4(aBh, t);
            bh[0][0] = t[0]; bh[0][1] = t[1]; bh[1][0] = t[2]; bh[1][1] = t[3];
            ldm_x4(aBh + 16 * TPAD * 2, t);
            bh[2][0] = t[0]; bh[2][1] = t[1]; bh[3][0] = t[2]; bh[3][1] = t[3];
            ldm_x4(aBl, t);
            bl[0][0] = t[0]; bl[0][1] = t[1]; bl[1][0] = t[2]; bl[1][1] = t[3];
            ldm_x4(aBl + 16 * TPAD * 2, t);
            bl[2][0] = t[0]; bl[2][1] = t[1]; bl[3][0] = t[2]; bl[3][1] = t[3];
        }
#pragma unroll
        for (int mt = 0; mt < 4; mt++)
            ldm_x4(aAh + mt * 16 * TPAD * 2, af[mt]);

        // cp.async burst for stage it+2 (overlaps with MMAs below)
        int nx = it + 2;
        if (nx < NK) load_stage(nx % NSTG, nx);
        CP_COMMIT();

#pragma unroll
        for (int mt = 0; mt < 4; mt++)
#pragma unroll
            for (int nt = 0; nt < 4; nt++) mma16816(acc[mt][nt], af[mt], bh[nt]);
#pragma unroll
        for (int mt = 0; mt < 4; mt++)
#pragma unroll
            for (int nt = 0; nt < 4; nt++) mma16816(acc[mt][nt], af[mt], bl[nt]);
#pragma unroll
        for (int mt = 0; mt < 4; mt++)
            ldm_x4(aAl + mt * 16 * TPAD * 2, af[mt]);
#pragma unroll
        for (int mt = 0; mt < 4; mt++)
#pragma unroll
            for (int nt = 0; nt < 4; nt++) mma16816(acc[mt][nt], af[mt], bh[nt]);

        // ---- ks = 1 (+32 bytes = 16 halves)
        {
            uint32_t t[4];
            ldm_x4(aBh + 32, t);
            bh[0][0] = t[0]; bh[0][1] = t[1]; bh[1][0] = t[2]; bh[1][1] = t[3];
            ldm_x4(aBh + 16 * TPAD * 2 + 32, t);
            bh[2][0] = t[0]; bh[2][1] = t[1]; bh[3][0] = t[2]; bh[3][1] = t[3];
            ldm_x4(aBl + 32, t);
            bl[0][0] = t[0]; bl[0][1] = t[1]; bl[1][0] = t[2]; bl[1][1] = t[3];
            ldm_x4(aBl + 16 * TPAD * 2 + 32, t);
            bl[2][0] = t[0]; bl[2][1] = t[1]; bl[3][0] = t[2]; bl[3][1] = t[3];
        }
#pragma unroll
        for (int mt = 0; mt < 4; mt++)
            ldm_x4(aAh + mt * 16 * TPAD * 2 + 32, af[mt]);
#pragma unroll
        for (int mt = 0; mt < 4; mt++)
#pragma unroll
            for (int nt = 0; nt < 4; nt++) mma16816(acc[mt][nt], af[mt], bh[nt]);
#pragma unroll
        for (int mt = 0; mt < 4; mt++)
#pragma unroll
            for (int nt = 0; nt < 4; nt++) mma16816(acc[mt][nt], af[mt], bl[nt]);
#pragma unroll
        for (int mt = 0; mt < 4; mt++)
            ldm_x4(aAl + mt * 16 * TPAD * 2 + 32, af[mt]);
#pragma unroll
        for (int mt = 0; mt < 4; mt++)
#pragma unroll
            for (int nt = 0; nt < 4; nt++) mma16816(acc[mt][nt], af[mt], bh[nt]);
    }

    // ---- epilogue: stage through smem for coalesced output ----
    __syncthreads();
    float* Csm = (float*)smem;                       // [256][132]
#pragma unroll
    for (int mt = 0; mt < 4; mt++) {
        int row = wm * 64 + mt * 16 + lr;
#pragma unroll
        for (int nt = 0; nt < 4; nt++) {
            int col = wn * 32 + nt * 8 + lc2;
            Csm[row * 132 + col]           = acc[mt][nt][0];
            Csm[row * 132 + col + 1]       = acc[mt][nt][1];
            Csm[(row + 8) * 132 + col]     = acc[mt][nt][2];
            Csm[(row + 8) * 132 + col + 1] = acc[mt][nt][3];
        }
    }
    __syncthreads();

    const int er = tid >> 5;          // 0..15 row group
    const int ec = (tid & 31) * 4;    // float4 col
    if (EPI == 0) {
        float s0 = 0.f, s1 = 0.f, s2 = 0.f, s3 = 0.f;
#pragma unroll
        for (int itr = 0; itr < 16; itr++) {
            int row = itr * 16 + er;
            float4 v = *(const float4*)(Csm + row * 132 + ec);
            s0 += __expf(v.x - MSHIFT); s1 += __expf(v.y - MSHIFT);
            s2 += __expf(v.z - MSHIFT); s3 += __expf(v.w - MSHIFT);
            *(float4*)(outS + (rowA0 + row) * SD + rowB0 + ec) = v;
        }
        float* Pm = Csm + 256 * 132;
        Pm[er * 128 + ec + 0] = s0; Pm[er * 128 + ec + 1] = s1;
        Pm[er * 128 + ec + 2] = s2; Pm[er * 128 + ec + 3] = s3;
        __syncthreads();
        if (tid < 128) {
            float s = Pm[tid];
#pragma unroll
            for (int r = 1; r < 16; r++) s += Pm[r * 128 + tid];
            g_colsum_part[by][rowB0 + tid] = s;   // fixed slot: deterministic
        }
    } else {
#pragma unroll
        for (int itr = 0; itr < 16; itr++) {
            int row = itr * 16 + er;
            float4 v = *(const float4*)(Csm + row * 132 + ec);
            if (dotanh) {
                v.x = tanhf(v.x); v.y = tanhf(v.y);
                v.z = tanhf(v.z); v.w = tanhf(v.w);
            }
            __half h0 = __float2half_rn(v.x), h1 = __float2half_rn(v.y);
            __half h2 = __float2half_rn(v.z), h3 = __float2half_rn(v.w);
            __half l0 = __float2half_rn(v.x - __half2float(h0));
            __half l1 = __float2half_rn(v.y - __half2float(h1));
            __half l2 = __float2half_rn(v.z - __half2float(h2));
            __half l3 = __float2half_rn(v.w - __half2float(h3));
            size_t o = (rowA0 + row) * HD + rowB0 + ec;
            __half2 hh0 = __halves2half2(h0, h1), hh1 = __halves2half2(h2, h3);
            __half2 ll0 = __halves2half2(l0, l1), ll1 = __halves2half2(l2, l3);
            uint2 hp, lp;
            hp.x = *(uint32_t*)&hh0; hp.y = *(uint32_t*)&hh1;
            lp.x = *(uint32_t*)&ll0; lp.y = *(uint32_t*)&ll1;
            *(uint2*)(outH + o) = hp;
            *(uint2*)(outL + o) = lp;
        }
    }
}

// ---------------- reduce partial column sums -> 1/sum -----------------------
__global__ void colsum_reduce_kernel() {
    const int j = blockIdx.x * blockDim.x + threadIdx.x;
    if (j >= SD) return;
    float s = 0.0f;
#pragma unroll
    for (int c = 0; c < NCHUNK; c++) s += g_colsum_part[c][j];
    g_colinv[j] = 1.0f / s;
}

// ---------------- attn = exp(s - 100) * inv_j -------------------------------
__global__ __launch_bounds__(256) void normalize_kernel(float* __restrict__ out) {
    const size_t gid = (size_t)blockIdx.x * blockDim.x + threadIdx.x;
    const size_t base = gid * 4;
    const int j = (int)(base & (SD - 1));
    float4 sc = *reinterpret_cast<const float4*>(g_scores + base);
    float4 iv = *reinterpret_cast<const float4*>(g_colinv + j);
    float4 r;
    r.x = __expf(sc.x - MSHIFT) * iv.x;
    r.y = __expf(sc.y - MSHIFT) * iv.y;
    r.z = __expf(sc.z - MSHIFT) * iv.z;
    r.w = __expf(sc.w - MSHIFT) * iv.w;
    *reinterpret_cast<float4*>(out + base) = r;
}

// ---------------- launch ----------------------------------------------------
extern "C" void kernel_launch(void* const* d_in, const int* in_sizes, int n_in,
                              void* d_out, int out_size) {
    const float* enc = (const float*)d_in[0];
    const float* w1  = (const float*)d_in[1];
    const float* w2  = (const float*)d_in[2];
    float* out = (float*)d_out;

    __half *eh, *el, *w1h, *w1l, *w2h, *w2l, *qh, *ql, *kh, *kl;
    cudaGetSymbolAddress((void**)&eh, g_eh);   cudaGetSymbolAddress((void**)&el, g_el);
    cudaGetSymbolAddress((void**)&w1h, g_w1h); cudaGetSymbolAddress((void**)&w1l, g_w1l);
    cudaGetSymbolAddress((void**)&w2h, g_w2h); cudaGetSymbolAddress((void**)&w2l, g_w2l);
    cudaGetSymbolAddress((void**)&qh, g_qh);   cudaGetSymbolAddress((void**)&ql, g_ql);
    cudaGetSymbolAddress((void**)&kh, g_kh);   cudaGetSymbolAddress((void**)&kl, g_kl);
    float* scores; cudaGetSymbolAddress((void**)&scores, g_scores);

    cudaFuncSetAttribute(gemm_hmma<0>, cudaFuncAttributeMaxDynamicSharedMemorySize, SMEM_TOTAL);
    cudaFuncSetAttribute(gemm_hmma<1>, cudaFuncAttributeMaxDynamicSharedMemorySize, SMEM_TOTAL);

    // 1. split inputs
    split_half_kernel<<<SD * HD / 4 / 256, 256>>>(enc, eh, el, SD * HD / 4);
    split_half_kernel<<<HD * HD / 4 / 256, 256>>>(w1, w1h, w1l, HD * HD / 4);
    split_half_kernel<<<HD * HD / 4 / 256, 256>>>(w2, w2h, w2l, HD * HD / 4);

    // 2. merged q/k: z=0 -> q=tanh(enc@w1^T), z=1 -> k=enc@w2^T
    gemm_hmma<1><<<dim3(HD / BN, SD / BM, 2), NT, SMEM_TOTAL>>>(
        eh, el, w1h, w1l, w2h, w2l, nullptr, qh, ql, kh, kl);

    // 3. scores = q@k^T (+ fused deterministic column exp-sums)
    gemm_hmma<0><<<dim3(SD / BN, SD / BM), NT, SMEM_TOTAL>>>(
        qh, ql, kh, kl, nullptr, nullptr, scores, nullptr, nullptr, nullptr, nullptr);

    // 4. reduce partials -> colinv
    colsum_reduce_kernel<<<SD / 256, 256>>>();

    // 5. attn
    normalize_kernel<<<(unsigned)((size_t)SD * SD / 4 / 256), 256>>>(out + (size_t)SD * HD);

    // 6. context = enc (col_sum == 1)
    cudaMemcpyAsync(out, enc, (size_t)SD * HD * sizeof(float),
                    cudaMemcpyDeviceToDevice);
}

// round 16
// speedup vs baseline: 1.0601x; 1.0601x over previous
#include <cuda_runtime.h>
#include <cuda_fp16.h>
#include <math.h>
#include <stdint.h>

#define SD 8192
#define HD 1024
#define NCHUNK 32                 // = SD / BM

#define BM 256
#define BN 128
#define BKH 32                    // K halves per chunk
#define TPAD 40                   // smem row stride (halves)
#define A_TILE_BYTES (BM * TPAD * 2)       // 20480
#define B_TILE_BYTES (BN * TPAD * 2)       // 10240
#define STAGE_BYTES (2 * A_TILE_BYTES + 2 * B_TILE_BYTES)  // 61440
#define NSTG 3
#define SMEM_TOTAL (NSTG * STAGE_BYTES)    // 184320
#define NK (HD / BKH)             // 32
#define MSHIFT 100.0f

// ---------------- device scratch (no allocations) --------------------------
static __device__ __half g_eh[SD * HD], g_el[SD * HD];
static __device__ __half g_w1h[HD * HD], g_w1l[HD * HD];
static __device__ __half g_w2h[HD * HD], g_w2l[HD * HD];
static __device__ __half g_qh[SD * HD], g_ql[SD * HD];
static __device__ __half g_kh[SD * HD], g_kl[SD * HD];
static __device__ float  g_scores[(size_t)SD * SD];
static __device__ float  g_colinv[SD];
static __device__ float  g_colsum_part[NCHUNK][SD];

// ---------------- helpers ---------------------------------------------------
__device__ __forceinline__ void cp16(uint32_t dst, const void* src) {
    asm volatile("cp.async.cg.shared.global [%0], [%1], 16;" :: "r"(dst), "l"(src));
}
#define CP_COMMIT() asm volatile("cp.async.commit_group;" ::: "memory")
#define CP_WAIT(n)  asm volatile("cp.async.wait_group %0;" :: "n"(n) : "memory")

__device__ __forceinline__ uint32_t smem_u32(const void* p) {
    uint32_t a;
    asm("{ .reg .u64 t; cvta.to.shared.u64 t, %1; cvt.u32.u64 %0, t; }"
        : "=r"(a) : "l"(p));
    return a;
}

__device__ __forceinline__ void mma16816(float* c, const uint32_t* a, const uint32_t* b) {
    asm volatile(
        "mma.sync.aligned.m16n8k16.row.col.f32.f16.f16.f32 "
        "{%0,%1,%2,%3}, {%4,%5,%6,%7}, {%8,%9}, {%0,%1,%2,%3};\n"
        : "+f"(c[0]), "+f"(c[1]), "+f"(c[2]), "+f"(c[3])
        : "r"(a[0]), "r"(a[1]), "r"(a[2]), "r"(a[3]), "r"(b[0]), "r"(b[1]));
}

__device__ __forceinline__ void ldm_x4(uint32_t addr, uint32_t* r) {
    asm volatile("ldmatrix.sync.aligned.m8n8.x4.shared.b16 {%0,%1,%2,%3}, [%4];"
        : "=r"(r[0]), "=r"(r[1]), "=r"(r[2]), "=r"(r[3]) : "r"(addr));
}

// ---------------- split fp32 -> fp16 hi/lo planes ---------------------------
__global__ __launch_bounds__(256) void split_half_kernel(
    const float* __restrict__ src, __half* __restrict__ hi,
    __half* __restrict__ lo, int n4) {
    int i = blockIdx.x * 256 + threadIdx.x;
    if (i >= n4) return;
    float4 v = ((const float4*)src)[i];
    __half h0 = __float2half_rn(v.x), h1 = __float2half_rn(v.y);
    __half h2 = __float2half_rn(v.z), h3 = __float2half_rn(v.w);
    __half l0 = __float2half_rn(v.x - __half2float(h0));
    __half l1 = __float2half_rn(v.y - __half2float(h1));
    __half l2 = __float2half_rn(v.z - __half2float(h2));
    __half l3 = __float2half_rn(v.w - __half2float(h3));
    ((__half2*)hi)[i * 2]     = __halves2half2(h0, h1);
    ((__half2*)hi)[i * 2 + 1] = __halves2half2(h2, h3);
    ((__half2*)lo)[i * 2]     = __halves2half2(l0, l1);
    ((__half2*)lo)[i * 2 + 1] = __halves2half2(l2, l3);
}

// ---------------- split-fp16 tensor-core GEMM: C[BM,BN] = A @ B^T -----------
// 256 threads, 8 warps in 4x2 grid, warp tile 64x64.
// Anti-phase skew: even warps do ks0->ks1, odd warps ks1->ks0, so each SMSP's
// two warps alternate ldmatrix and MMA phases (fills tensor-pipe gaps).
// EPI 0: scores + fused deterministic column exp-sums (shift M=100)
// EPI 1: merged q/k — blockIdx.z picks weights/outputs; z==0 applies tanh
template <int EPI>
__global__ __launch_bounds__(256, 1) void gemm_hmma(
    const __half* __restrict__ Ah, const __half* __restrict__ Al,
    const __half* __restrict__ B1h, const __half* __restrict__ B1l,
    const __half* __restrict__ B2h, const __half* __restrict__ B2l,
    float* __restrict__ outS,
    __half* __restrict__ o1H, __half* __restrict__ o1L,
    __half* __restrict__ o2H, __half* __restrict__ o2L) {
    extern __shared__ char smem[];
    const uint32_t su_base = smem_u32(smem);
    const int tid = threadIdx.x;
    const int wid = tid >> 5, lane = tid & 31;
    const int wm = wid >> 1, wn = wid & 1;       // warp 64x64 tiles: 4x2 grid
    const int lr = lane >> 2, lc2 = (lane & 3) * 2;

    const int z = (EPI == 1) ? blockIdx.z : 0;
    const __half* Bh = (EPI == 1 && z) ? B2h : B1h;
    const __half* Bl = (EPI == 1 && z) ? B2l : B1l;
    __half* outH = (EPI == 1) ? (z ? o2H : o1H) : (__half*)0;
    __half* outL = (EPI == 1) ? (z ? o2L : o1L) : (__half*)0;
    const bool dotanh = (EPI == 1) && (z == 0);

    // supertile remap (8 M-tiles per N panel stay L2-hot)
    int id = blockIdx.y * gridDim.x + blockIdx.x;
    const int G = 8;
    int perG = gridDim.x * G;
    int by = (id / perG) * G + ((id % perG) % G);
    int bx = (id % perG) / G;

    const size_t rowA0 = (size_t)by * BM;
    const size_t rowB0 = (size_t)bx * BN;

    // ldmatrix per-lane byte offsets within a tile
    const uint32_t aoff =
        ((uint32_t)((wm * 64 + (lane & 7) + ((lane >> 3) & 1) * 8) * TPAD +
                    ((lane >> 4) & 1) * 8)) * 2;
    const uint32_t boff =
        ((uint32_t)((wn * 64 + ((lane >> 4) & 1) * 8 + (lane & 7)) * TPAD +
                    ((lane >> 3) & 1) * 8)) * 2;

    // anti-phase: odd warps process the second K-half first
    const uint32_t kfirst = (wid & 1) ? 32u : 0u;
    const uint32_t ksecond = kfirst ^ 32u;

    float acc[4][8][4];
#pragma unroll
    for (int a = 0; a < 4; a++)
#pragma unroll
        for (int b = 0; b < 8; b++)
#pragma unroll
            for (int c = 0; c < 4; c++) acc[a][b][c] = 0.0f;

    // ---- async load one k-chunk into stage s (12 cp16 per thread) ----
    auto load_stage = [&](int s, int kc) {
        const int k0 = kc * BKH;
        uint32_t sb = su_base + s * STAGE_BYTES;
#pragma unroll
        for (int t = 0; t < 8; t++) {          // A planes: idx 0..2047
            int idx = tid + t * 256;
            int plane = idx >> 10;
            int r = (idx >> 2) & 255;
            int c = idx & 3;
            const __half* src = (plane ? Al : Ah) + (rowA0 + r) * HD + k0 + c * 8;
            cp16(sb + plane * A_TILE_BYTES + (r * TPAD + c * 8) * 2, src);
        }
#pragma unroll
        for (int t = 0; t < 4; t++) {          // B planes: idx 0..1023
            int idx = tid + t * 256;
            int plane = idx >> 9;
            int r = (idx >> 2) & 127;
            int c = idx & 3;
            const __half* src = (plane ? Bl : Bh) + (rowB0 + r) * HD + k0 + c * 8;
            cp16(sb + 2 * A_TILE_BYTES + plane * B_TILE_BYTES + (r * TPAD + c * 8) * 2, src);
        }
    };

    load_stage(0, 0); CP_COMMIT();
    load_stage(1, 1); CP_COMMIT();

    for (int it = 0; it < NK; it++) {
        CP_WAIT(1);
        __syncthreads();
        const uint32_t sbase = su_base + (it % NSTG) * STAGE_BYTES;
        const uint32_t aAh = sbase + aoff;
        const uint32_t aAl = sbase + A_TILE_BYTES + aoff;
        const uint32_t aBh = sbase + 2 * A_TILE_BYTES + boff;
        const uint32_t aBl = sbase + 2 * A_TILE_BYTES + B_TILE_BYTES + boff;

        uint32_t bh[8][2], bl[8][2], af[4][4];
        // ---- first K-half (kfirst): fragment loads, then cp burst, then MMAs
#pragma unroll
        for (int p = 0; p < 4; p++) {
            uint32_t t[4];
            ldm_x4(aBh + p * 16 * TPAD * 2 + kfirst, t);
            bh[p * 2][0] = t[0]; bh[p * 2][1] = t[1];
            bh[p * 2 + 1][0] = t[2]; bh[p * 2 + 1][1] = t[3];
        }
#pragma unroll
        for (int p = 0; p < 4; p++) {
            uint32_t t[4];
            ldm_x4(aBl + p * 16 * TPAD * 2 + kfirst, t);
            bl[p * 2][0] = t[0]; bl[p * 2][1] = t[1];
            bl[p * 2 + 1][0] = t[2]; bl[p * 2 + 1][1] = t[3];
        }
#pragma unroll
        for (int mt = 0; mt < 4; mt++)
            ldm_x4(aAh + mt * 16 * TPAD * 2 + kfirst, af[mt]);

        // cp.async burst for stage it+2 (overlaps with MMAs below)
        int nx = it + 2;
        if (nx < NK) load_stage(nx % NSTG, nx);
        CP_COMMIT();

#pragma unroll
        for (int mt = 0; mt < 4; mt++)
#pragma unroll
            for (int nt = 0; nt < 8; nt++) mma16816(acc[mt][nt], af[mt], bh[nt]);
#pragma unroll
        for (int mt = 0; mt < 4; mt++)
#pragma unroll
            for (int nt = 0; nt < 8; nt++) mma16816(acc[mt][nt], af[mt], bl[nt]);
#pragma unroll
        for (int mt = 0; mt < 4; mt++)
            ldm_x4(aAl + mt * 16 * TPAD * 2 + kfirst, af[mt]);
#pragma unroll
        for (int mt = 0; mt < 4; mt++)
#pragma unroll
            for (int nt = 0; nt < 8; nt++) mma16816(acc[mt][nt], af[mt], bh[nt]);

        // ---- second K-half (ksecond)
#pragma unroll
        for (int p = 0; p < 4; p++) {
            uint32_t t[4];
            ldm_x4(aBh + p * 16 * TPAD * 2 + ksecond, t);
            bh[p * 2][0] = t[0]; bh[p * 2][1] = t[1];
            bh[p * 2 + 1][0] = t[2]; bh[p * 2 + 1][1] = t[3];
        }
#pragma unroll
        for (int p = 0; p < 4; p++) {
            uint32_t t[4];
            ldm_x4(aBl + p * 16 * TPAD * 2 + ksecond, t);
            bl[p * 2][0] = t[0]; bl[p * 2][1] = t[1];
            bl[p * 2 + 1][0] = t[2]; bl[p * 2 + 1][1] = t[3];
        }
#pragma unroll
        for (int mt = 0; mt < 4; mt++)
            ldm_x4(aAh + mt * 16 * TPAD * 2 + ksecond, af[mt]);
#pragma unroll
        for (int mt = 0; mt < 4; mt++)
#pragma unroll
            for (int nt = 0; nt < 8; nt++) mma16816(acc[mt][nt], af[mt], bh[nt]);
#pragma unroll
        for (int mt = 0; mt < 4; mt++)
#pragma unroll
            for (int nt = 0; nt < 8; nt++) mma16816(acc[mt][nt], af[mt], bl[nt]);
#pragma unroll
        for (int mt = 0; mt < 4; mt++)
            ldm_x4(aAl + mt * 16 * TPAD * 2 + ksecond, af[mt]);
#pragma unroll
        for (int mt = 0; mt < 4; mt++)
#pragma unroll
            for (int nt = 0; nt < 8; nt++) mma16816(acc[mt][nt], af[mt], bh[nt]);
    }

    // ---- epilogue: stage through smem for coalesced output ----
    __syncthreads();
    float* Csm = (float*)smem;                       // [256][132]
#pragma unroll
    for (int mt = 0; mt < 4; mt++) {
        int row = wm * 64 + mt * 16 + lr;
#pragma unroll
        for (int nt = 0; nt < 8; nt++) {
            int col = wn * 64 + nt * 8 + lc2;
            Csm[row * 132 + col]           = acc[mt][nt][0];
            Csm[row * 132 + col + 1]       = acc[mt][nt][1];
            Csm[(row + 8) * 132 + col]     = acc[mt][nt][2];
            Csm[(row + 8) * 132 + col + 1] = acc[mt][nt][3];
        }
    }
    __syncthreads();

    const int er = tid >> 5;          // 0..7 row group
    const int ec = (tid & 31) * 4;    // float4 col
    if (EPI == 0) {
        float s0 = 0.f, s1 = 0.f, s2 = 0.f, s3 = 0.f;
#pragma unroll
        for (int itr = 0; itr < 32; itr++) {
            int row = itr * 8 + er;
            float4 v = *(const float4*)(Csm + row * 132 + ec);
            s0 += __expf(v.x - MSHIFT); s1 += __expf(v.y - MSHIFT);
            s2 += __expf(v.z - MSHIFT); s3 += __expf(v.w - MSHIFT);
            *(float4*)(outS + (rowA0 + row) * SD + rowB0 + ec) = v;
        }
        float* Pm = Csm + 256 * 132;
        Pm[er * 128 + ec + 0] = s0; Pm[er * 128 + ec + 1] = s1;
        Pm[er * 128 + ec + 2] = s2; Pm[er * 128 + ec + 3] = s3;
        __syncthreads();
        if (tid < 128) {
            float s = Pm[tid];
#pragma unroll
            for (int r = 1; r < 8; r++) s += Pm[r * 128 + tid];
            g_colsum_part[by][rowB0 + tid] = s;   // fixed slot: deterministic
        }
    } else {
#pragma unroll
        for (int itr = 0; itr < 32; itr++) {
            int row = itr * 8 + er;
            float4 v = *(const float4*)(Csm + row * 132 + ec);
            if (dotanh) {
                v.x = tanhf(v.x); v.y = tanhf(v.y);
                v.z = tanhf(v.z); v.w = tanhf(v.w);
            }
            __half h0 = __float2half_rn(v.x), h1 = __float2half_rn(v.y);
            __half h2 = __float2half_rn(v.z), h3 = __float2half_rn(v.w);
            __half l0 = __float2half_rn(v.x - __half2float(h0));
            __half l1 = __float2half_rn(v.y - __half2float(h1));
            __half l2 = __float2half_rn(v.z - __half2float(h2));
            __half l3 = __float2half_rn(v.w - __half2float(h3));
            size_t o = (rowA0 + row) * HD + rowB0 + ec;
            __half2 hh0 = __halves2half2(h0, h1), hh1 = __halves2half2(h2, h3);
            __half2 ll0 = __halves2half2(l0, l1), ll1 = __halves2half2(l2, l3);
            uint2 hp, lp;
            hp.x = *(uint32_t*)&hh0; hp.y = *(uint32_t*)&hh1;
            lp.x = *(uint32_t*)&ll0; lp.y = *(uint32_t*)&ll1;
            *(uint2*)(outH + o) = hp;
            *(uint2*)(outL + o) = lp;
        }
    }
}

// ---------------- reduce partial column sums -> 1/sum -----------------------
__global__ void colsum_reduce_kernel() {
    const int j = blockIdx.x * blockDim.x + threadIdx.x;
    if (j >= SD) return;
    float s = 0.0f;
#pragma unroll
    for (int c = 0; c < NCHUNK; c++) s += g_colsum_part[c][j];
    g_colinv[j] = 1.0f / s;
}

// ---------------- attn = exp(s - 100) * inv_j -------------------------------
__global__ __launch_bounds__(256) void normalize_kernel(float* __restrict__ out) {
    const size_t gid = (size_t)blockIdx.x * blockDim.x + threadIdx.x;
    const size_t base = gid * 4;
    const int j = (int)(base & (SD - 1));
    float4 sc = *reinterpret_cast<const float4*>(g_scores + base);
    float4 iv = *reinterpret_cast<const float4*>(g_colinv + j);
    float4 r;
    r.x = __expf(sc.x - MSHIFT) * iv.x;
    r.y = __expf(sc.y - MSHIFT) * iv.y;
    r.z = __expf(sc.z - MSHIFT) * iv.z;
    r.w = __expf(sc.w - MSHIFT) * iv.w;
    *reinterpret_cast<float4*>(out + base) = r;
}

// ---------------- launch ----------------------------------------------------
extern "C" void kernel_launch(void* const* d_in, const int* in_sizes, int n_in,
                              void* d_out, int out_size) {
    const float* enc = (const float*)d_in[0];
    const float* w1  = (const float*)d_in[1];
    const float* w2  = (const float*)d_in[2];
    float* out = (float*)d_out;

    __half *eh, *el, *w1h, *w1l, *w2h, *w2l, *qh, *ql, *kh, *kl;
    cudaGetSymbolAddress((void**)&eh, g_eh);   cudaGetSymbolAddress((void**)&el, g_el);
    cudaGetSymbolAddress((void**)&w1h, g_w1h); cudaGetSymbolAddress((void**)&w1l, g_w1l);
    cudaGetSymbolAddress((void**)&w2h, g_w2h); cudaGetSymbolAddress((void**)&w2l, g_w2l);
    cudaGetSymbolAddress((void**)&qh, g_qh);   cudaGetSymbolAddress((void**)&ql, g_ql);
    cudaGetSymbolAddress((void**)&kh, g_kh);   cudaGetSymbolAddress((void**)&kl, g_kl);
    float* scores; cudaGetSymbolAddress((void**)&scores, g_scores);

    cudaFuncSetAttribute(gemm_hmma<0>, cudaFuncAttributeMaxDynamicSharedMemorySize, SMEM_TOTAL);
    cudaFuncSetAttribute(gemm_hmma<1>, cudaFuncAttributeMaxDynamicSharedMemorySize, SMEM_TOTAL);

    // 1. split inputs
    split_half_kernel<<<SD * HD / 4 / 256, 256>>>(enc, eh, el, SD * HD / 4);
    split_half_kernel<<<HD * HD / 4 / 256, 256>>>(w1, w1h, w1l, HD * HD / 4);
    split_half_kernel<<<HD * HD / 4 / 256, 256>>>(w2, w2h, w2l, HD * HD / 4);

    // 2. merged q/k: z=0 -> q=tanh(enc@w1^T), z=1 -> k=enc@w2^T
    gemm_hmma<1><<<dim3(HD / BN, SD / BM, 2), 256, SMEM_TOTAL>>>(
        eh, el, w1h, w1l, w2h, w2l, nullptr, qh, ql, kh, kl);

    // 3. scores = q@k^T (+ fused deterministic column exp-sums)
    gemm_hmma<0><<<dim3(SD / BN, SD / BM), 256, SMEM_TOTAL>>>(
        qh, ql, kh, kl, nullptr, nullptr, scores, nullptr, nullptr, nullptr, nullptr);

    // 4. reduce partials -> colinv
    colsum_reduce_kernel<<<SD / 256, 256>>>();

    // 5. attn
    normalize_kernel<<<(unsigned)((size_t)SD * SD / 4 / 256), 256>>>(out + (size_t)SD * HD);

    // 6. context = enc (col_sum == 1)
    cudaMemcpyAsync(out, enc, (size_t)SD * HD * sizeof(float),
                    cudaMemcpyDeviceToDevice);
}